// round 15
// baseline (speedup 1.0000x reference)
#include <cuda_runtime.h>
#include <cstdint>

#define N 256
#define NP 65536
#define NVOX 16777216u
#define YC 64
#define NSTEPS 68            // YC + 4; epilogue at t in [4,67]

// ---------------- packed f32x2 helpers (sm_103a) ----------------
union F2U { float2 f; unsigned long long u; };
__device__ __forceinline__ float2 f2add(float2 a, float2 b) {
    F2U x, y, r; x.f = a; y.f = b;
    asm("add.rn.f32x2 %0,%1,%2;" : "=l"(r.u) : "l"(x.u), "l"(y.u));
    return r.f;
}
__device__ __forceinline__ float2 f2mul(float2 a, float2 b) {
    F2U x, y, r; x.f = a; y.f = b;
    asm("mul.rn.f32x2 %0,%1,%2;" : "=l"(r.u) : "l"(x.u), "l"(y.u));
    return r.f;
}
__device__ __forceinline__ float2 f2fma(float2 a, float2 b, float2 c) {
    F2U x, y, zc, r; x.f = a; y.f = b; zc.f = c;
    asm("fma.rn.f32x2 %0,%1,%2,%3;" : "=l"(r.u) : "l"(x.u), "l"(y.u), "l"(zc.u));
    return r.f;
}
__device__ __forceinline__ float2 f2set(float a, float b) { float2 r; r.x = a; r.y = b; return r; }

// ===========================================================================
// Fused NCC forces, 2 voxels/thread, interleaved smem (R12 structure),
// register diet for 5 CTAs/SM: ez/sc rings moved to smem / recomputed,
// single-reciprocal epilogue.
// ===========================================================================
__global__ __launch_bounds__(128, 5) void ncc_fused9_kernel(
    const float* __restrict__ img, const float* __restrict__ ref,
    float* __restrict__ out)
{
    __shared__ __align__(16) float2 q01[2][260];   // (sum_i, sum_r) interleaved
    __shared__ __align__(16) float2 q23[2][260];   // (sum_ii, sum_rr) interleaved
    __shared__ __align__(16) float  qir_s[2][264]; // sum_ir scalar row
    __shared__ __align__(16) float2 ccp[5][260];   // center row ring (img, ref)
    __shared__ __align__(16) float2 ezs[5][128];   // per-thread z-gradient ring

    const int t0 = threadIdx.x;       // 0..127
    const int x0 = t0 << 1;
    const int z  = blockIdx.x;
    const int y0 = blockIdx.y * YC;

    // zero pads once
    {
        int pi = t0 & 3;
        int pidx = (pi < 2) ? pi : (pi + 256);
        if (t0 < 8)        q01[t0 >> 2][pidx] = f2set(0.f, 0.f);
        else if (t0 < 16)  q23[(t0 >> 2) & 1][pidx] = f2set(0.f, 0.f);
        else if (t0 < 36)  ccp[(t0 - 16) >> 2][pidx] = f2set(0.f, 0.f);
        else if (t0 < 44)  qir_s[(t0 - 36) >> 2][pidx] = 0.f;
    }

    bool pz[5]; int pb[5];
#pragma unroll
    for (int p = 0; p < 5; p++) {
        int zz = z - 2 + p;
        pz[p] = (zz >= 0) && (zz < N);
        pb[p] = (pz[p] ? zz : 0) * NP + x0;
    }

    const float2 zero2 = f2set(0.f, 0.f);
    const float2 km1   = f2set(-1.f, -1.f);
    const float2 km2   = f2set(-2.f, -2.f);
    const float2 k05   = f2set(0.5f, 0.5f);
    const float2 k025  = f2set(0.25f, 0.25f);
    const float2 k2    = f2set(2.f, 2.f);
    const float2 kinv  = f2set(1.f / 125.f, 1.f / 125.f);
    const float2 keps  = f2set(1e-6f, 1e-6f);

    // y-box value ring, statically indexed by unroll phase j
    float2 ring[5][5];
#pragma unroll
    for (int q = 0; q < 5; q++)
#pragma unroll
        for (int k = 0; k < 5; k++) ring[q][k] = zero2;

    const bool z_lo = (z == 0);
    const bool z_hi = (z == N - 1);

    // prefetch row t=0 (yl = y0-2); incremental row offset, predicated loads
    float2 pvi[5], pvr[5];
    int yn = y0 - 2;
    int ro = yn * N;
    {
        bool inr = ((unsigned)yn < (unsigned)N);
#pragma unroll
        for (int p = 0; p < 5; p++) {
            bool ok = inr && pz[p];
            pvi[p] = ok ? __ldg((const float2*)(img + pb[p] + ro)) : zero2;
            pvr[p] = ok ? __ldg((const float2*)(ref + pb[p] + ro)) : zero2;
        }
        yn += 1; ro += N;
    }
    __syncthreads();

    unsigned oidx = (unsigned)z * (unsigned)NP + (unsigned)y0 * N + (unsigned)x0;

    int buf = 0;
    for (int tb = 0; tb < 14; ++tb) {
#pragma unroll
        for (int j = 0; j < 5; ++j) {
            const int t = tb * 5 + j;
            if (t >= NSTEPS) break;   // uniform across CTA

            // ---- z-summed quantities (packed) ----
            const float2 v0 = pvi[0], v1 = pvi[1], v2 = pvi[2], v3 = pvi[3], v4 = pvi[4];
            const float2 r0 = pvr[0], r1 = pvr[1], r2 = pvr[2], r3 = pvr[3], r4 = pvr[4];
            const float2 qi   = f2add(f2add(f2add(v0, v1), f2add(v2, v3)), v4);
            const float2 qr   = f2add(f2add(f2add(r0, r1), f2add(r2, r3)), r4);
            const float2 qii  = f2fma(v4, v4, f2fma(v3, v3, f2fma(v2, v2, f2fma(v1, v1, f2mul(v0, v0)))));
            const float2 qrr  = f2fma(r4, r4, f2fma(r3, r3, f2fma(r2, r2, f2fma(r1, r1, f2mul(r0, r0)))));
            const float2 qirv = f2fma(v4, r4, f2fma(v3, r3, f2fma(v2, r2, f2fma(v1, r1, f2mul(v0, r0)))));

            // ---- z-gradient pair sums -> per-thread smem ring ----
            {
                const float2 s_cc = f2add(v2, r2);
                const float2 s_zp = f2add(v3, r3);
                const float2 s_zm = f2add(v1, r1);
                float2 ezv;
                if (z_lo)      ezv = f2mul(f2fma(s_cc, km1, s_zp), k2);
                else if (z_hi) ezv = f2mul(f2fma(s_zm, km1, s_cc), k2);
                else           ezv = f2fma(s_zm, km1, s_zp);
                ezs[j][t0] = ezv;
            }

            // ---- interleaved smem stores ----
            *(float4*)&q01[buf][x0 + 2] = make_float4(qi.x, qr.x, qi.y, qr.y);
            *(float4*)&q23[buf][x0 + 2] = make_float4(qii.x, qrr.x, qii.y, qrr.y);
            *(float2*)&qir_s[buf][x0 + 2] = qirv;
            *(float4*)&ccp[j][x0 + 2] = make_float4(v2.x, r2.x, v2.y, r2.y);

            // ---- prefetch next row (incremental offset) ----
            if (t + 1 < NSTEPS) {
                bool inr = ((unsigned)yn < (unsigned)N);
#pragma unroll
                for (int p = 0; p < 5; p++) {
                    bool ok = inr && pz[p];
                    pvi[p] = ok ? __ldg((const float2*)(img + pb[p] + ro)) : zero2;
                    pvr[p] = ok ? __ldg((const float2*)(ref + pb[p] + ro)) : zero2;
                }
                yn += 1; ro += N;
            }
            __syncthreads();

            // ---- x-box (own values in regs, paired neighbor loads) ----
            {
                float4 L = *(const float4*)&q01[buf][x0];
                float4 R = *(const float4*)&q01[buf][x0 + 4];
                float si = L.z + qi.x + qi.y + R.x;
                ring[0][j] = f2set(si + L.x, si + R.z);
                float sr = L.w + qr.x + qr.y + R.y;
                ring[1][j] = f2set(sr + L.y, sr + R.w);
            }
            {
                float4 L = *(const float4*)&q23[buf][x0];
                float4 R = *(const float4*)&q23[buf][x0 + 4];
                float sii = L.z + qii.x + qii.y + R.x;
                ring[2][j] = f2set(sii + L.x, sii + R.z);
                float srr = L.w + qrr.x + qrr.y + R.y;
                ring[3][j] = f2set(srr + L.y, srr + R.w);
            }
            {
                float2 L = *(const float2*)&qir_s[buf][x0];
                float2 R = *(const float2*)&qir_s[buf][x0 + 4];
                float s = L.y + qirv.x + qirv.y + R.x;
                ring[4][j] = f2set(s + L.x, s + R.y);
            }
            buf ^= 1;

            // ---- epilogue for y = y0 + t - 4 ----
            if (t >= 4) {
                const int y = y0 + t - 4;
                const int jc = (j + 3) % 5;
                const int jp = (j + 4) % 5;
                const int jm = (j + 2) % 5;

                const float2 sum_i  = f2add(f2add(f2add(ring[0][0], ring[0][1]), f2add(ring[0][2], ring[0][3])), ring[0][4]);
                const float2 sum_r  = f2add(f2add(f2add(ring[1][0], ring[1][1]), f2add(ring[1][2], ring[1][3])), ring[1][4]);
                const float2 sum_ii = f2add(f2add(f2add(ring[2][0], ring[2][1]), f2add(ring[2][2], ring[2][3])), ring[2][4]);
                const float2 sum_rr = f2add(f2add(f2add(ring[3][0], ring[3][1]), f2add(ring[3][2], ring[3][3])), ring[3][4]);
                const float2 sum_ir = f2add(f2add(f2add(ring[4][0], ring[4][1]), f2add(ring[4][2], ring[4][3])), ring[4][4]);

                // mr = mi (faithful); 125*mi folded to sum_i (error ~1e-7 rel)
                const float2 mi = f2mul(sum_i, kinv);
                const float2 nmi = f2mul(mi, km1);
                const float2 varr = f2fma(mi, f2fma(sum_r, km2, sum_i), sum_rr);
                const float2 vari = f2fma(nmi, sum_i, sum_ii);
                const float2 cross = f2fma(nmi, sum_r, sum_ir);

                // center row reads
                const float4 C  = *(const float4*)&ccp[jc][x0 + 2];
                const float2 P  = ccp[jc][x0 + 1];
                const float2 Nx = ccp[jc][x0 + 4];
                const float2 ciI = f2set(C.x, C.z);
                const float2 ciR = f2set(C.y, C.w);

                // x gradient
                const float2 xsl = f2set(P.x + P.y, C.x + C.y);
                const float2 xsr = f2set(C.z + C.w, Nx.x + Nx.y);
                float2 gw = f2mul(f2fma(xsl, km1, xsr), k025);
                const float ge = 0.5f * ((C.z - C.x) + (C.w - C.y));
                if (t0 == 0)   gw.x = ge;
                if (t0 == 127) gw.y = ge;

                // y gradient: (I+R) pair sums recomputed from ccp rows
                const float2 scc_c = f2add(ciI, ciR);
                const float4 Cp = *(const float4*)&ccp[jp][x0 + 2];
                const float4 Cm = *(const float4*)&ccp[jm][x0 + 2];
                const float2 scc_p = f2set(Cp.x + Cp.y, Cp.z + Cp.w);
                const float2 scc_m = f2set(Cm.x + Cm.y, Cm.z + Cm.w);
                float2 gh;
                if (y == 0)          gh = f2mul(f2fma(scc_c, km1, scc_p), k05);
                else if (y == N - 1) gh = f2mul(f2fma(scc_m, km1, scc_c), k05);
                else                 gh = f2mul(f2fma(scc_m, km1, scc_p), k025);

                // z gradient from per-thread smem ring
                const float2 gd = f2mul(ezs[jc][t0], k025);

                // single-reciprocal force:
                // factor = 2*cross*(ciI*varr - cross*ciR) / ((vari*varr+eps)*varr)
                const float2 den = f2mul(f2fma(vari, varr, keps), varr);
                float2 rd;
                rd.x = __fdividef(1.f, den.x);
                rd.y = __fdividef(1.f, den.y);
                const float2 tIV = f2mul(ciI, varr);
                const float2 num = f2fma(cross, ciR, f2mul(tIV, km1));   // cross*ciR - ciI*varr
                // nfac = -factor = 2*cross*rd*num  (sign folded via negated num)
                const float2 nfac = f2mul(f2mul(k2, cross), f2mul(rd, num));

                *(float2*)(out + oidx)             = f2mul(nfac, gd);
                *(float2*)(out + NVOX + oidx)      = f2mul(nfac, gh);
                *(float2*)(out + 2u * NVOX + oidx) = f2mul(nfac, gw);
                oidx += N;
            }
        }
    }
}

// ---------------------------------------------------------------------------
extern "C" void kernel_launch(void* const* d_in, const int* in_sizes, int n_in,
                              void* d_out, int out_size)
{
    const float* img = (const float*)d_in[0];   // image
    const float* ref = (const float*)d_in[2];   // reference_image
    float* out = (float*)d_out;

    dim3 block(128, 1, 1);
    dim3 grid(N, N / YC, 1);    // 256 z x 4 y-chunks = 1024 CTAs
    ncc_fused9_kernel<<<grid, block>>>(img, ref, out);
}

// round 16
// speedup vs baseline: 1.0676x; 1.0676x over previous
#include <cuda_runtime.h>
#include <cstdint>

#define N 256
#define NP 65536
#define NVOX 16777216u
#define YC 64
#define NSTEPS 68            // YC + 4; epilogue at t in [4,67]

// ---------------- packed f32x2 helpers (sm_103a) ----------------
union F2U { float2 f; unsigned long long u; };
__device__ __forceinline__ float2 f2add(float2 a, float2 b) {
    F2U x, y, r; x.f = a; y.f = b;
    asm("add.rn.f32x2 %0,%1,%2;" : "=l"(r.u) : "l"(x.u), "l"(y.u));
    return r.f;
}
__device__ __forceinline__ float2 f2mul(float2 a, float2 b) {
    F2U x, y, r; x.f = a; y.f = b;
    asm("mul.rn.f32x2 %0,%1,%2;" : "=l"(r.u) : "l"(x.u), "l"(y.u));
    return r.f;
}
__device__ __forceinline__ float2 f2fma(float2 a, float2 b, float2 c) {
    F2U x, y, zc, r; x.f = a; y.f = b; zc.f = c;
    asm("fma.rn.f32x2 %0,%1,%2,%3;" : "=l"(r.u) : "l"(x.u), "l"(y.u), "l"(zc.u));
    return r.f;
}
__device__ __forceinline__ float2 f2set(float a, float b) { float2 r; r.x = a; r.y = b; return r; }

// ===========================================================================
// Fused NCC forces, 2 voxels/thread (R12 structure), single-reciprocal
// epilogue, incremental output index, trimmed tail steps. 4 CTAs/SM.
// ===========================================================================
__global__ __launch_bounds__(128, 4) void ncc_fused10_kernel(
    const float* __restrict__ img, const float* __restrict__ ref,
    float* __restrict__ out)
{
    __shared__ __align__(16) float2 q01[2][260];   // (sum_i, sum_r) interleaved
    __shared__ __align__(16) float2 q23[2][260];   // (sum_ii, sum_rr) interleaved
    __shared__ __align__(16) float  qir_s[2][264]; // sum_ir scalar row
    __shared__ __align__(16) float2 ccp[5][260];   // center row ring (img, ref)

    const int t0 = threadIdx.x;       // 0..127
    const int x0 = t0 << 1;
    const int z  = blockIdx.x;
    const int y0 = blockIdx.y * YC;

    // zero pads once
    {
        int pi = t0 & 3;
        int pidx = (pi < 2) ? pi : (pi + 256);
        if (t0 < 8)        q01[t0 >> 2][pidx] = f2set(0.f, 0.f);
        else if (t0 < 16)  q23[(t0 >> 2) & 1][pidx] = f2set(0.f, 0.f);
        else if (t0 < 36)  ccp[(t0 - 16) >> 2][pidx] = f2set(0.f, 0.f);
        else if (t0 < 44)  qir_s[(t0 - 36) >> 2][pidx] = 0.f;
    }

    bool pz[5]; int pb[5];
#pragma unroll
    for (int p = 0; p < 5; p++) {
        int zz = z - 2 + p;
        pz[p] = (zz >= 0) && (zz < N);
        pb[p] = (pz[p] ? zz : 0) * NP + x0;
    }

    const float2 zero2 = f2set(0.f, 0.f);
    const float2 km1   = f2set(-1.f, -1.f);
    const float2 km2   = f2set(-2.f, -2.f);
    const float2 k05   = f2set(0.5f, 0.5f);
    const float2 k025  = f2set(0.25f, 0.25f);
    const float2 k2    = f2set(2.f, 2.f);
    const float2 kinv  = f2set(1.f / 125.f, 1.f / 125.f);
    const float2 keps  = f2set(1e-6f, 1e-6f);

    // statically indexed rings (slot = t mod 5)
    float2 ring[5][5];    // x-boxed quantities (y-box window)
    float2 ez[5];         // encoded z-gradient pair sums
    float2 sc[5];         // center pair sums v2+r2 (y-gradient)
#pragma unroll
    for (int k = 0; k < 5; k++) {
        ez[k] = zero2; sc[k] = zero2;
#pragma unroll
        for (int q = 0; q < 5; q++) ring[q][k] = zero2;
    }

    const bool z_lo = (z == 0);
    const bool z_hi = (z == N - 1);

    // prefetch row t=0 (yl = y0-2); incremental row offset, predicated loads
    float2 pvi[5], pvr[5];
    int yn = y0 - 2;
    int ro = yn * N;
    {
        bool inr = ((unsigned)yn < (unsigned)N);
#pragma unroll
        for (int p = 0; p < 5; p++) {
            bool ok = inr && pz[p];
            pvi[p] = ok ? __ldg((const float2*)(img + pb[p] + ro)) : zero2;
            pvr[p] = ok ? __ldg((const float2*)(ref + pb[p] + ro)) : zero2;
        }
        yn += 1; ro += N;
    }
    __syncthreads();

    unsigned oidx = (unsigned)z * (unsigned)NP + (unsigned)y0 * N + (unsigned)x0;

    int buf = 0;
    for (int tb = 0; tb < 14; ++tb) {
#pragma unroll
        for (int j = 0; j < 5; ++j) {
            const int t = tb * 5 + j;
            if (t >= NSTEPS) break;   // uniform across CTA (only in last block)

            // ---- z-summed quantities (packed) ----
            const float2 v0 = pvi[0], v1 = pvi[1], v2 = pvi[2], v3 = pvi[3], v4 = pvi[4];
            const float2 r0 = pvr[0], r1 = pvr[1], r2 = pvr[2], r3 = pvr[3], r4 = pvr[4];
            const float2 qi   = f2add(f2add(f2add(v0, v1), f2add(v2, v3)), v4);
            const float2 qr   = f2add(f2add(f2add(r0, r1), f2add(r2, r3)), r4);
            const float2 qii  = f2fma(v4, v4, f2fma(v3, v3, f2fma(v2, v2, f2fma(v1, v1, f2mul(v0, v0)))));
            const float2 qrr  = f2fma(r4, r4, f2fma(r3, r3, f2fma(r2, r2, f2fma(r1, r1, f2mul(r0, r0)))));
            const float2 qirv = f2fma(v4, r4, f2fma(v3, r3, f2fma(v2, r2, f2fma(v1, r1, f2mul(v0, r0)))));

            // ---- gradient pair-sum rings ----
            const float2 s_cc = f2add(v2, r2);
            const float2 s_zp = f2add(v3, r3);
            const float2 s_zm = f2add(v1, r1);
            float2 ezv;
            if (z_lo)      ezv = f2mul(f2fma(s_cc, km1, s_zp), k2);
            else if (z_hi) ezv = f2mul(f2fma(s_zm, km1, s_cc), k2);
            else           ezv = f2fma(s_zm, km1, s_zp);
            ez[j] = ezv;
            sc[j] = s_cc;

            // ---- interleaved smem stores ----
            *(float4*)&q01[buf][x0 + 2] = make_float4(qi.x, qr.x, qi.y, qr.y);
            *(float4*)&q23[buf][x0 + 2] = make_float4(qii.x, qrr.x, qii.y, qrr.y);
            *(float2*)&qir_s[buf][x0 + 2] = qirv;
            *(float4*)&ccp[j][x0 + 2] = make_float4(v2.x, r2.x, v2.y, r2.y);

            // ---- prefetch next row (incremental offset) ----
            if (t + 1 < NSTEPS) {
                bool inr = ((unsigned)yn < (unsigned)N);
#pragma unroll
                for (int p = 0; p < 5; p++) {
                    bool ok = inr && pz[p];
                    pvi[p] = ok ? __ldg((const float2*)(img + pb[p] + ro)) : zero2;
                    pvr[p] = ok ? __ldg((const float2*)(ref + pb[p] + ro)) : zero2;
                }
                yn += 1; ro += N;
            }
            __syncthreads();

            // ---- x-box (own values in regs, paired neighbor loads) ----
            {
                float4 L = *(const float4*)&q01[buf][x0];
                float4 R = *(const float4*)&q01[buf][x0 + 4];
                float si = L.z + qi.x + qi.y + R.x;
                ring[0][j] = f2set(si + L.x, si + R.z);
                float sr = L.w + qr.x + qr.y + R.y;
                ring[1][j] = f2set(sr + L.y, sr + R.w);
            }
            {
                float4 L = *(const float4*)&q23[buf][x0];
                float4 R = *(const float4*)&q23[buf][x0 + 4];
                float sii = L.z + qii.x + qii.y + R.x;
                ring[2][j] = f2set(sii + L.x, sii + R.z);
                float srr = L.w + qrr.x + qrr.y + R.y;
                ring[3][j] = f2set(srr + L.y, srr + R.w);
            }
            {
                float2 L = *(const float2*)&qir_s[buf][x0];
                float2 R = *(const float2*)&qir_s[buf][x0 + 4];
                float s = L.y + qirv.x + qirv.y + R.x;
                ring[4][j] = f2set(s + L.x, s + R.y);
            }
            buf ^= 1;

            // ---- epilogue for y = y0 + t - 4 ----
            if (t >= 4) {
                const int y = y0 + t - 4;
                const int jc = (j + 3) % 5;
                const int jp = (j + 4) % 5;
                const int jm = (j + 2) % 5;

                const float2 sum_i  = f2add(f2add(f2add(ring[0][0], ring[0][1]), f2add(ring[0][2], ring[0][3])), ring[0][4]);
                const float2 sum_r  = f2add(f2add(f2add(ring[1][0], ring[1][1]), f2add(ring[1][2], ring[1][3])), ring[1][4]);
                const float2 sum_ii = f2add(f2add(f2add(ring[2][0], ring[2][1]), f2add(ring[2][2], ring[2][3])), ring[2][4]);
                const float2 sum_rr = f2add(f2add(f2add(ring[3][0], ring[3][1]), f2add(ring[3][2], ring[3][3])), ring[3][4]);
                const float2 sum_ir = f2add(f2add(f2add(ring[4][0], ring[4][1]), f2add(ring[4][2], ring[4][3])), ring[4][4]);

                // mr = mi (faithful); 125*mi folded to sum_i (error ~1e-7 rel)
                const float2 mi = f2mul(sum_i, kinv);
                const float2 nmi = f2mul(mi, km1);
                const float2 varr = f2fma(mi, f2fma(sum_r, km2, sum_i), sum_rr);
                const float2 vari = f2fma(nmi, sum_i, sum_ii);
                const float2 cross = f2fma(nmi, sum_r, sum_ir);

                // center row reads
                const float4 C  = *(const float4*)&ccp[jc][x0 + 2];
                const float2 P  = ccp[jc][x0 + 1];
                const float2 Nx = ccp[jc][x0 + 4];
                const float2 ciI = f2set(C.x, C.z);
                const float2 ciR = f2set(C.y, C.w);

                // x gradient
                const float2 xsl = f2set(P.x + P.y, C.x + C.y);
                const float2 xsr = f2set(C.z + C.w, Nx.x + Nx.y);
                float2 gw = f2mul(f2fma(xsl, km1, xsr), k025);
                const float ge = 0.5f * ((C.z - C.x) + (C.w - C.y));
                if (t0 == 0)   gw.x = ge;
                if (t0 == 127) gw.y = ge;

                // y gradient from sc ring
                float2 gh;
                if (y == 0)          gh = f2mul(f2fma(sc[jc], km1, sc[jp]), k05);
                else if (y == N - 1) gh = f2mul(f2fma(sc[jm], km1, sc[jc]), k05);
                else                 gh = f2mul(f2fma(sc[jm], km1, sc[jp]), k025);

                // z gradient
                const float2 gd = f2mul(ez[jc], k025);

                // single-reciprocal force:
                // -factor = 2*cross*(cross*ciR - ciI*varr) / ((vari*varr+eps)*varr)
                const float2 den = f2mul(f2fma(vari, varr, keps), varr);
                float2 rd;
                rd.x = __fdividef(1.f, den.x);
                rd.y = __fdividef(1.f, den.y);
                const float2 num = f2fma(cross, ciR, f2mul(f2mul(ciI, varr), km1));
                const float2 nfac = f2mul(f2mul(k2, cross), f2mul(rd, num));

                *(float2*)(out + oidx)             = f2mul(nfac, gd);
                *(float2*)(out + NVOX + oidx)      = f2mul(nfac, gh);
                *(float2*)(out + 2u * NVOX + oidx) = f2mul(nfac, gw);
                oidx += N;
            }
        }
    }
}

// ---------------------------------------------------------------------------
extern "C" void kernel_launch(void* const* d_in, const int* in_sizes, int n_in,
                              void* d_out, int out_size)
{
    const float* img = (const float*)d_in[0];   // image
    const float* ref = (const float*)d_in[2];   // reference_image
    float* out = (float*)d_out;

    dim3 block(128, 1, 1);
    dim3 grid(N, N / YC, 1);    // 256 z x 4 y-chunks = 1024 CTAs
    ncc_fused10_kernel<<<grid, block>>>(img, ref, out);
}